// round 1
// baseline (speedup 1.0000x reference)
#include <cuda_runtime.h>
#include <cuda_bf16.h>
#include <stdint.h>

#define NR 8192
#define DD 512
#define BM 128
#define BN 128
#define BK 32
#define SST 72            // smem row stride in bf16 (144 B: 16B-aligned, conflict-free for ldmatrix)
#define NSTRIPX 64        // NR/BN column strips
#define NPART (NSTRIPX*2) // two warp_n halves write separate partials (determinism, no atomics)

// ---- device scratch (no allocations allowed) ----
__device__ __align__(16) __nv_bfloat16 g_ne[NR * DD];   // 8 MB normalized embeddings, bf16
__device__ float g_pos[NR];
__device__ float g_Spart[NPART][NR];                    // 4 MB partial exp-sums
__device__ float g_rowval[NR];

// ============================================================
// Kernel A: row-normalize embeddings -> bf16, compute pos_i
// ============================================================
__global__ void norm_kernel(const float* __restrict__ emb, const float* __restrict__ tgt) {
    int row = blockIdx.x;
    int t = threadIdx.x; // 128 threads
    const float* e  = emb + (size_t)row * DD;
    const float* tg = tgt + (size_t)row * DD;

    float ev[4], tv[4];
    float ee = 0.f, tt = 0.f, et = 0.f;
#pragma unroll
    for (int j = 0; j < 4; j++) {
        ev[j] = e[t + 128 * j];
        tv[j] = tg[t + 128 * j];
        ee += ev[j] * ev[j];
        tt += tv[j] * tv[j];
        et += ev[j] * tv[j];
    }
#pragma unroll
    for (int o = 16; o > 0; o >>= 1) {
        ee += __shfl_xor_sync(0xFFFFFFFFu, ee, o);
        tt += __shfl_xor_sync(0xFFFFFFFFu, tt, o);
        et += __shfl_xor_sync(0xFFFFFFFFu, et, o);
    }
    __shared__ float sred[3][4];
    int w = t >> 5, l = t & 31;
    if (l == 0) { sred[0][w] = ee; sred[1][w] = tt; sred[2][w] = et; }
    __syncthreads();
    ee = sred[0][0] + sred[0][1] + sred[0][2] + sred[0][3];
    tt = sred[1][0] + sred[1][1] + sred[1][2] + sred[1][3];
    et = sred[2][0] + sred[2][1] + sred[2][2] + sred[2][3];

    float inv_e = rsqrtf(ee);
    if (t == 0) g_pos[row] = et * inv_e * rsqrtf(tt);
#pragma unroll
    for (int j = 0; j < 4; j++)
        g_ne[(size_t)row * DD + t + 128 * j] = __float2bfloat16(ev[j] * inv_e);
}

// ============================================================
// Kernel B: fused ne @ ne^T with exp(2x) row-sum epilogue
//   128x128 block tile, 8 warps (4 m x 2 n), warp tile 32x64
//   mma.sync.m16n8k16 bf16 -> f32
// ============================================================
__device__ __forceinline__ void ldsm_x4(uint32_t& r0, uint32_t& r1, uint32_t& r2, uint32_t& r3,
                                        uint32_t addr) {
    asm volatile("ldmatrix.sync.aligned.m8n8.x4.shared.b16 {%0,%1,%2,%3}, [%4];"
                 : "=r"(r0), "=r"(r1), "=r"(r2), "=r"(r3) : "r"(addr));
}

__device__ __forceinline__ void mma_bf16(float c[4], const uint32_t a[4], uint32_t b0, uint32_t b1) {
    asm volatile(
        "mma.sync.aligned.m16n8k16.row.col.f32.bf16.bf16.f32 "
        "{%0,%1,%2,%3}, {%4,%5,%6,%7}, {%8,%9}, {%0,%1,%2,%3};"
        : "+f"(c[0]), "+f"(c[1]), "+f"(c[2]), "+f"(c[3])
        : "r"(a[0]), "r"(a[1]), "r"(a[2]), "r"(a[3]), "r"(b0), "r"(b1));
}

__global__ __launch_bounds__(256, 2) void gemm_lse_kernel() {
    __shared__ __align__(16) __nv_bfloat16 As[BM * SST];
    __shared__ __align__(16) __nv_bfloat16 Bs[BN * SST];

    const int tid = threadIdx.x;
    const int lane = tid & 31;
    const int wid = tid >> 5;
    const int warp_m = wid >> 1;   // 0..3
    const int warp_n = wid & 1;    // 0..1
    const int row0 = blockIdx.x * BM;
    const int col0 = blockIdx.y * BN;

    float acc[2][8][4];
#pragma unroll
    for (int mi = 0; mi < 2; mi++)
#pragma unroll
        for (int ni = 0; ni < 8; ni++)
#pragma unroll
            for (int k = 0; k < 4; k++) acc[mi][ni][k] = 0.f;

    const uint32_t asmem = (uint32_t)__cvta_generic_to_shared(As);
    const uint32_t bsmem = (uint32_t)__cvta_generic_to_shared(Bs);

    // ldmatrix per-lane addressing
    const int arow = (lane & 7) + ((lane >> 3) & 1) * 8;
    const int akb  = (lane >> 4) * 16;
    const int brow = (lane & 7) + ((lane >> 4) << 3);
    const int bkb  = ((lane >> 3) & 1) * 16;

    uint32_t a_addr[2], b_addr[4];
#pragma unroll
    for (int mi = 0; mi < 2; mi++)
        a_addr[mi] = asmem + (uint32_t)((warp_m * 32 + mi * 16 + arow) * (SST * 2) + akb);
#pragma unroll
    for (int nj = 0; nj < 4; nj++)
        b_addr[nj] = bsmem + (uint32_t)((warp_n * 64 + nj * 16 + brow) * (SST * 2) + bkb);

    for (int kt = 0; kt < DD / BK; kt++) {
        __syncthreads();
        // load 128x32 bf16 A and B tiles: 512 x 16B chunks each, 2 per thread
#pragma unroll
        for (int i = 0; i < 2; i++) {
            int c = tid + 256 * i;
            int r = c >> 2;
            int kc = (c & 3) * 8;
            const uint4* srcA = reinterpret_cast<const uint4*>(
                &g_ne[(size_t)(row0 + r) * DD + kt * BK + kc]);
            *reinterpret_cast<uint4*>(&As[r * SST + kc]) = *srcA;
            const uint4* srcB = reinterpret_cast<const uint4*>(
                &g_ne[(size_t)(col0 + r) * DD + kt * BK + kc]);
            *reinterpret_cast<uint4*>(&Bs[r * SST + kc]) = *srcB;
        }
        __syncthreads();

#pragma unroll
        for (int ks = 0; ks < 2; ks++) {
            uint32_t a[2][4], b[4][4];
#pragma unroll
            for (int mi = 0; mi < 2; mi++)
                ldsm_x4(a[mi][0], a[mi][1], a[mi][2], a[mi][3], a_addr[mi] + ks * 32);
#pragma unroll
            for (int nj = 0; nj < 4; nj++)
                ldsm_x4(b[nj][0], b[nj][1], b[nj][2], b[nj][3], b_addr[nj] + ks * 32);
#pragma unroll
            for (int mi = 0; mi < 2; mi++)
#pragma unroll
                for (int ni = 0; ni < 8; ni++)
                    mma_bf16(acc[mi][ni], a[mi], b[ni >> 1][(ni & 1) * 2], b[ni >> 1][(ni & 1) * 2 + 1]);
        }
    }

    // Epilogue: exp(2*cos) row sums. Fragment rows: lane>>2 and lane>>2 + 8.
    float rs[2][2];
    rs[0][0] = rs[0][1] = rs[1][0] = rs[1][1] = 0.f;
#pragma unroll
    for (int mi = 0; mi < 2; mi++)
#pragma unroll
        for (int ni = 0; ni < 8; ni++) {
            rs[mi][0] += __expf(acc[mi][ni][0] + acc[mi][ni][0]) +
                         __expf(acc[mi][ni][1] + acc[mi][ni][1]);
            rs[mi][1] += __expf(acc[mi][ni][2] + acc[mi][ni][2]) +
                         __expf(acc[mi][ni][3] + acc[mi][ni][3]);
        }
    // reduce across the 4 lanes (bits 0-1) sharing each row
#pragma unroll
    for (int mi = 0; mi < 2; mi++)
#pragma unroll
        for (int h = 0; h < 2; h++) {
            rs[mi][h] += __shfl_xor_sync(0xFFFFFFFFu, rs[mi][h], 1);
            rs[mi][h] += __shfl_xor_sync(0xFFFFFFFFu, rs[mi][h], 2);
        }
    if ((lane & 3) == 0) {
        int strip = blockIdx.y * 2 + warp_n;
#pragma unroll
        for (int mi = 0; mi < 2; mi++) {
            int r = row0 + warp_m * 32 + mi * 16 + (lane >> 2);
            g_Spart[strip][r]     = rs[mi][0];
            g_Spart[strip][r + 8] = rs[mi][1];
        }
    }
}

// ============================================================
// Kernel C1: per-row logsumexp combine  (deterministic fixed order)
// ============================================================
__global__ void rowval_kernel() {
    int row = blockIdx.x * 256 + threadIdx.x;
    float s = 0.f;
#pragma unroll 8
    for (int p = 0; p < NPART; p++) s += g_Spart[p][row];
    g_rowval[row] = logf(s) - 2.f * g_pos[row];
}

// ============================================================
// Kernel C2: final scalar reduce
// ============================================================
__global__ void final_kernel(float* __restrict__ out) {
    int t = threadIdx.x; // 256
    float s = 0.f;
    for (int k = t; k < NR; k += 256) s += g_rowval[k];
#pragma unroll
    for (int o = 16; o > 0; o >>= 1) s += __shfl_xor_sync(0xFFFFFFFFu, s, o);
    __shared__ float sw[8];
    if ((t & 31) == 0) sw[t >> 5] = s;
    __syncthreads();
    if (t == 0) {
        float tot = 0.f;
#pragma unroll
        for (int w = 0; w < 8; w++) tot += sw[w];
        out[0] = tot * (1.0f / (2.0f * NR));
    }
}

// ============================================================
extern "C" void kernel_launch(void* const* d_in, const int* in_sizes, int n_in,
                              void* d_out, int out_size) {
    const float* emb = (const float*)d_in[0];
    const float* tgt = (const float*)d_in[1];
    float* out = (float*)d_out;

    norm_kernel<<<NR, 128>>>(emb, tgt);
    dim3 grid(NR / BM, NR / BN);
    gemm_lse_kernel<<<grid, 256>>>();
    rowval_kernel<<<NR / 256, 256>>>();
    final_kernel<<<1, 256>>>(out);
}

// round 3
// speedup vs baseline: 2.0274x; 2.0274x over previous
#include <cuda_runtime.h>
#include <cuda_bf16.h>
#include <stdint.h>

#define NR 8192
#define DD 512
#define BM 128
#define BK 32
#define NKT (DD / BK)        // 16 k-tiles
#define NBLK (NR / BM)       // 64
#define NTRI (NBLK * (NBLK + 1) / 2)   // 2080 upper-triangle tiles
#define STAGES 4
#define SSTB 80                       // smem row stride in BYTES (conflict-free ldmatrix)
#define TILE_SMEM (BM * SSTB)         // 10240 B per operand tile
#define STAGE_SMEM (2 * TILE_SMEM)    // 20480 B (A + B)
#define SMEM_TOTAL (STAGES * STAGE_SMEM)

// ---- device scratch (no allocations allowed) ----
__device__ __align__(16) __nv_bfloat16 g_ne[NR * DD];   // 8 MB normalized embeddings
__device__ float g_pos[NR];
__device__ float g_Spart[NBLK][NR];                     // 2 MB partial exp-sums
__device__ float g_rowval[NR];

// ============================================================
// Kernel A: row-normalize embeddings -> bf16, compute pos_i
// ============================================================
__global__ void norm_kernel(const float* __restrict__ emb, const float* __restrict__ tgt) {
    int row = blockIdx.x;
    int t = threadIdx.x; // 128
    const float* e  = emb + (size_t)row * DD;
    const float* tg = tgt + (size_t)row * DD;

    float ev[4], tv[4];
    float ee = 0.f, tt = 0.f, et = 0.f;
#pragma unroll
    for (int j = 0; j < 4; j++) {
        ev[j] = e[t + 128 * j];
        tv[j] = tg[t + 128 * j];
        ee += ev[j] * ev[j];
        tt += tv[j] * tv[j];
        et += ev[j] * tv[j];
    }
#pragma unroll
    for (int o = 16; o > 0; o >>= 1) {
        ee += __shfl_xor_sync(0xFFFFFFFFu, ee, o);
        tt += __shfl_xor_sync(0xFFFFFFFFu, tt, o);
        et += __shfl_xor_sync(0xFFFFFFFFu, et, o);
    }
    __shared__ float sred[3][4];
    int w = t >> 5, l = t & 31;
    if (l == 0) { sred[0][w] = ee; sred[1][w] = tt; sred[2][w] = et; }
    __syncthreads();
    ee = sred[0][0] + sred[0][1] + sred[0][2] + sred[0][3];
    tt = sred[1][0] + sred[1][1] + sred[1][2] + sred[1][3];
    et = sred[2][0] + sred[2][1] + sred[2][2] + sred[2][3];

    float inv_e = rsqrtf(ee);
    if (t == 0) g_pos[row] = et * inv_e * rsqrtf(tt);
#pragma unroll
    for (int j = 0; j < 4; j++)
        g_ne[(size_t)row * DD + t + 128 * j] = __float2bfloat16(ev[j] * inv_e);
}

// ============================================================
// MMA helpers
// ============================================================
__device__ __forceinline__ void ldsm_x4(uint32_t& r0, uint32_t& r1, uint32_t& r2, uint32_t& r3,
                                        uint32_t addr) {
    asm volatile("ldmatrix.sync.aligned.m8n8.x4.shared.b16 {%0,%1,%2,%3}, [%4];"
                 : "=r"(r0), "=r"(r1), "=r"(r2), "=r"(r3) : "r"(addr));
}

__device__ __forceinline__ void mma_bf16(float c[4], const uint32_t a[4], uint32_t b0, uint32_t b1) {
    asm volatile(
        "mma.sync.aligned.m16n8k16.row.col.f32.bf16.bf16.f32 "
        "{%0,%1,%2,%3}, {%4,%5,%6,%7}, {%8,%9}, {%0,%1,%2,%3};"
        : "+f"(c[0]), "+f"(c[1]), "+f"(c[2]), "+f"(c[3])
        : "r"(a[0]), "r"(a[1]), "r"(a[2]), "r"(a[3]), "r"(b0), "r"(b1));
}

__device__ __forceinline__ void cp16(uint32_t dst, const void* src) {
    asm volatile("cp.async.cg.shared.global [%0], [%1], 16;" :: "r"(dst), "l"(src));
}
__device__ __forceinline__ void cp_commit() {
    asm volatile("cp.async.commit_group;" ::: "memory");
}
template <int N>
__device__ __forceinline__ void cp_wait() {
    asm volatile("cp.async.wait_group %0;" :: "n"(N) : "memory");
}

// ============================================================
// Kernel B: upper-triangle ne @ ne^T, 4-stage cp.async pipeline,
//   exp(2x) row+col sums (symmetry). 128x128 tile, 256 thr, occ 2.
// ============================================================
__global__ void __launch_bounds__(256, 2) gemm_lse_kernel() {
    extern __shared__ char smem[];
    const uint32_t sb = (uint32_t)__cvta_generic_to_shared(smem);

    const int tid = threadIdx.x;
    const int lane = tid & 31;
    const int wid = tid >> 5;
    const int warp_m = wid >> 1;   // 0..3
    const int warp_n = wid & 1;    // 0..1

    // ---- decode upper-triangle tile index -> (bi, bj), bi <= bj ----
    int t = blockIdx.x;
    int bi = (int)(64.5f - sqrtf(64.5f * 64.5f - 2.0f * (float)t));
    if (bi < 0) bi = 0;
    if (bi > 63) bi = 63;
#define TRI_S(b) ((b) * 64 - ((b) * ((b) - 1)) / 2)
    while (bi > 0 && TRI_S(bi) > t) bi--;
    while (bi < 63 && TRI_S(bi + 1) <= t) bi++;
    const int bj = bi + (t - TRI_S(bi));
    const bool diag = (bi == bj);

    const __nv_bfloat16* gA = g_ne + (size_t)bi * BM * DD;
    const __nv_bfloat16* gB = g_ne + (size_t)bj * BM * DD;

    // per-thread cp.async chunk coords (2 chunks of 16B per operand)
    const int r0c = tid >> 2;                 // chunk set 0 row
    const int r1c = (tid + 256) >> 2;         // chunk set 1 row
    const int kc0 = (tid & 3) * 8;
    const int kc1 = ((tid + 256) & 3) * 8;    // == kc0, but keep general

    // ldmatrix per-lane addressing (byte offsets within a tile)
    const int arow = (lane & 7) + ((lane >> 3) & 1) * 8;
    const int akb  = (lane >> 4) * 16;
    const int brow = (lane & 7) + ((lane >> 4) << 3);
    const int bkb  = ((lane >> 3) & 1) * 16;
    const uint32_t aoff0 = (uint32_t)((warp_m * 32 + arow) * SSTB + akb);
    const uint32_t aoff1 = aoff0 + 16 * SSTB;
    uint32_t boff[4];
#pragma unroll
    for (int nj = 0; nj < 4; nj++)
        boff[nj] = (uint32_t)((warp_n * 64 + nj * 16 + brow) * SSTB + bkb) + TILE_SMEM;

    float acc[2][8][4];
#pragma unroll
    for (int mi = 0; mi < 2; mi++)
#pragma unroll
        for (int ni = 0; ni < 8; ni++)
#pragma unroll
            for (int k = 0; k < 4; k++) acc[mi][ni][k] = 0.f;

    // ---- pipeline prologue: fill STAGES-1 stages ----
#pragma unroll
    for (int p = 0; p < STAGES - 1; p++) {
        uint32_t base = sb + p * STAGE_SMEM;
        cp16(base + r0c * SSTB + kc0 * 2, gA + (size_t)r0c * DD + p * BK + kc0);
        cp16(base + r1c * SSTB + kc1 * 2, gA + (size_t)r1c * DD + p * BK + kc1);
        cp16(base + TILE_SMEM + r0c * SSTB + kc0 * 2, gB + (size_t)r0c * DD + p * BK + kc0);
        cp16(base + TILE_SMEM + r1c * SSTB + kc1 * 2, gB + (size_t)r1c * DD + p * BK + kc1);
        cp_commit();
    }

    for (int kt = 0; kt < NKT; kt++) {
        // issue load for kt+STAGES-1
        int kl = kt + STAGES - 1;
        if (kl < NKT) {
            uint32_t base = sb + (kl & (STAGES - 1)) * STAGE_SMEM;
            cp16(base + r0c * SSTB + kc0 * 2, gA + (size_t)r0c * DD + kl * BK + kc0);
            cp16(base + r1c * SSTB + kc1 * 2, gA + (size_t)r1c * DD + kl * BK + kc1);
            cp16(base + TILE_SMEM + r0c * SSTB + kc0 * 2, gB + (size_t)r0c * DD + kl * BK + kc0);
            cp16(base + TILE_SMEM + r1c * SSTB + kc1 * 2, gB + (size_t)r1c * DD + kl * BK + kc1);
        }
        cp_commit();
        cp_wait<STAGES - 2>();
        __syncthreads();

        uint32_t base = sb + (kt & (STAGES - 1)) * STAGE_SMEM;
#pragma unroll
        for (int ks = 0; ks < 2; ks++) {
            uint32_t a[2][4], b[4][4];
            ldsm_x4(a[0][0], a[0][1], a[0][2], a[0][3], base + aoff0 + ks * 32);
            ldsm_x4(a[1][0], a[1][1], a[1][2], a[1][3], base + aoff1 + ks * 32);
#pragma unroll
            for (int nj = 0; nj < 4; nj++)
                ldsm_x4(b[nj][0], b[nj][1], b[nj][2], b[nj][3], base + boff[nj] + ks * 32);
#pragma unroll
            for (int mi = 0; mi < 2; mi++)
#pragma unroll
                for (int ni = 0; ni < 8; ni++)
                    mma_bf16(acc[mi][ni], a[mi], b[ni >> 1][(ni & 1) * 2], b[ni >> 1][(ni & 1) * 2 + 1]);
        }
        __syncthreads();
    }

    // ---- epilogue: exp(2x); row sums always, col sums if off-diagonal ----
#pragma unroll
    for (int mi = 0; mi < 2; mi++)
#pragma unroll
        for (int ni = 0; ni < 8; ni++)
#pragma unroll
            for (int k = 0; k < 4; k++) {
                float x = acc[mi][ni][k];
                acc[mi][ni][k] = __expf(x + x);
            }

    // reduction buffers alias pipeline smem (all compute done, all warps synced)
    float* rowbuf = (float*)smem;               // [2][128]
    float* colbuf = (float*)(smem + 1024);      // [4][128]

    // row sums: reduce over n-fragments and lanes 1,2 (col lanes)
#pragma unroll
    for (int mi = 0; mi < 2; mi++) {
        float r0 = 0.f, r1 = 0.f;
#pragma unroll
        for (int ni = 0; ni < 8; ni++) {
            r0 += acc[mi][ni][0] + acc[mi][ni][1];
            r1 += acc[mi][ni][2] + acc[mi][ni][3];
        }
        r0 += __shfl_xor_sync(0xFFFFFFFFu, r0, 1);
        r0 += __shfl_xor_sync(0xFFFFFFFFu, r0, 2);
        r1 += __shfl_xor_sync(0xFFFFFFFFu, r1, 1);
        r1 += __shfl_xor_sync(0xFFFFFFFFu, r1, 2);
        if ((lane & 3) == 0) {
            int rr = warp_m * 32 + mi * 16 + (lane >> 2);
            rowbuf[warp_n * 128 + rr] = r0;
            rowbuf[warp_n * 128 + rr + 8] = r1;
        }
    }

    // col sums: reduce over m-fragments and lanes 4,8,16 (row lanes)
    if (!diag) {
#pragma unroll
        for (int ni = 0; ni < 8; ni++) {
            float ce = acc[0][ni][0] + acc[0][ni][2] + acc[1][ni][0] + acc[1][ni][2];
            float co = acc[0][ni][1] + acc[0][ni][3] + acc[1][ni][1] + acc[1][ni][3];
            ce += __shfl_xor_sync(0xFFFFFFFFu, ce, 4);
            ce += __shfl_xor_sync(0xFFFFFFFFu, ce, 8);
            ce += __shfl_xor_sync(0xFFFFFFFFu, ce, 16);
            co += __shfl_xor_sync(0xFFFFFFFFu, co, 4);
            co += __shfl_xor_sync(0xFFFFFFFFu, co, 8);
            co += __shfl_xor_sync(0xFFFFFFFFu, co, 16);
            if (lane < 4) {
                int cc = warp_n * 64 + ni * 8 + lane * 2;
                colbuf[warp_m * 128 + cc] = ce;
                colbuf[warp_m * 128 + cc + 1] = co;
            }
        }
    }
    __syncthreads();

    if (tid < 128) {
        g_Spart[bj][bi * BM + tid] = rowbuf[tid] + rowbuf[128 + tid];
        if (!diag)
            g_Spart[bi][bj * BM + tid] =
                colbuf[tid] + colbuf[128 + tid] + colbuf[256 + tid] + colbuf[384 + tid];
    }
}

// ============================================================
// Kernel C1: per-row combine (deterministic fixed order)
// ============================================================
__global__ void rowval_kernel() {
    int row = blockIdx.x * 256 + threadIdx.x;
    float s = 0.f;
#pragma unroll 8
    for (int p = 0; p < NBLK; p++) s += g_Spart[p][row];
    g_rowval[row] = logf(s) - 2.f * g_pos[row];
}

// ============================================================
// Kernel C2: final scalar reduce
// ============================================================
__global__ void final_kernel(float* __restrict__ out) {
    int t = threadIdx.x; // 256
    float s = 0.f;
    for (int k = t; k < NR; k += 256) s += g_rowval[k];
#pragma unroll
    for (int o = 16; o > 0; o >>= 1) s += __shfl_xor_sync(0xFFFFFFFFu, s, o);
    __shared__ float sw[8];
    if ((t & 31) == 0) sw[t >> 5] = s;
    __syncthreads();
    if (t == 0) {
        float tot = 0.f;
#pragma unroll
        for (int w = 0; w < 8; w++) tot += sw[w];
        out[0] = tot * (1.0f / (2.0f * NR));
    }
}

// ============================================================
extern "C" void kernel_launch(void* const* d_in, const int* in_sizes, int n_in,
                              void* d_out, int out_size) {
    const float* emb = (const float*)d_in[0];
    const float* tgt = (const float*)d_in[1];
    float* out = (float*)d_out;

    cudaFuncSetAttribute(gemm_lse_kernel, cudaFuncAttributeMaxDynamicSharedMemorySize, SMEM_TOTAL);

    norm_kernel<<<NR, 128>>>(emb, tgt);
    gemm_lse_kernel<<<NTRI, 256, SMEM_TOTAL>>>();
    rowval_kernel<<<NR / 256, 256>>>();
    final_kernel<<<1, 256>>>(out);
}

// round 4
// speedup vs baseline: 2.1664x; 1.0686x over previous
#include <cuda_runtime.h>
#include <cuda_bf16.h>
#include <cuda_fp8.h>
#include <stdint.h>

#define NR 8192
#define DD 512
#define BM 128
#define BKB 64               // k bytes (fp8 elems) per stage row
#define NKT (DD / BKB)       // 8 k-tiles
#define NBLK (NR / BM)       // 64
#define NTRI (NBLK * (NBLK + 1) / 2)   // 2080 upper-triangle tiles
#define STAGES 4
#define SSTB 80                       // smem row stride bytes (conflict-free ldmatrix)
#define TILE_SMEM (BM * SSTB)         // 10240 B per operand tile
#define STAGE_SMEM (2 * TILE_SMEM)    // 20480 B
#define SMEM_TOTAL (STAGES * STAGE_SMEM)  // 81920 B

// ---- device scratch (no allocations allowed) ----
__device__ __align__(16) uint8_t g_ne[NR * DD];         // 4 MB fp8 normalized embeddings
__device__ float g_pos[NR];
__device__ float g_Spart[NBLK][NR];                     // 2 MB partial exp-sums
__device__ float g_blocksum[32];

// ============================================================
// Kernel A: row-normalize embeddings -> e4m3, compute pos_i
// ============================================================
__global__ void norm_kernel(const float* __restrict__ emb, const float* __restrict__ tgt) {
    int row = blockIdx.x;
    int t = threadIdx.x; // 128
    const float* e  = emb + (size_t)row * DD;
    const float* tg = tgt + (size_t)row * DD;

    float ev[4], tv[4];
    float ee = 0.f, tt = 0.f, et = 0.f;
#pragma unroll
    for (int j = 0; j < 4; j++) {
        ev[j] = e[t + 128 * j];
        tv[j] = tg[t + 128 * j];
        ee += ev[j] * ev[j];
        tt += tv[j] * tv[j];
        et += ev[j] * tv[j];
    }
#pragma unroll
    for (int o = 16; o > 0; o >>= 1) {
        ee += __shfl_xor_sync(0xFFFFFFFFu, ee, o);
        tt += __shfl_xor_sync(0xFFFFFFFFu, tt, o);
        et += __shfl_xor_sync(0xFFFFFFFFu, et, o);
    }
    __shared__ float sred[3][4];
    int w = t >> 5, l = t & 31;
    if (l == 0) { sred[0][w] = ee; sred[1][w] = tt; sred[2][w] = et; }
    __syncthreads();
    ee = sred[0][0] + sred[0][1] + sred[0][2] + sred[0][3];
    tt = sred[1][0] + sred[1][1] + sred[1][2] + sred[1][3];
    et = sred[2][0] + sred[2][1] + sred[2][2] + sred[2][3];

    float inv_e = rsqrtf(ee);
    if (t == 0) g_pos[row] = et * inv_e * rsqrtf(tt);
#pragma unroll
    for (int j = 0; j < 4; j++) {
        __nv_fp8_storage_t v =
            __nv_cvt_float_to_fp8(ev[j] * inv_e, __NV_SATFINITE, __NV_E4M3);
        g_ne[(size_t)row * DD + t + 128 * j] = (uint8_t)v;
    }
}

// ============================================================
// MMA helpers (fp8 e4m3, m16n8k32)
// ============================================================
__device__ __forceinline__ void ldsm_x4(uint32_t& r0, uint32_t& r1, uint32_t& r2, uint32_t& r3,
                                        uint32_t addr) {
    asm volatile("ldmatrix.sync.aligned.m8n8.x4.shared.b16 {%0,%1,%2,%3}, [%4];"
                 : "=r"(r0), "=r"(r1), "=r"(r2), "=r"(r3) : "r"(addr));
}

__device__ __forceinline__ void mma_fp8(float c[4], const uint32_t a[4], uint32_t b0, uint32_t b1) {
    asm volatile(
        "mma.sync.aligned.m16n8k32.row.col.f32.e4m3.e4m3.f32 "
        "{%0,%1,%2,%3}, {%4,%5,%6,%7}, {%8,%9}, {%0,%1,%2,%3};"
        : "+f"(c[0]), "+f"(c[1]), "+f"(c[2]), "+f"(c[3])
        : "r"(a[0]), "r"(a[1]), "r"(a[2]), "r"(a[3]), "r"(b0), "r"(b1));
}

__device__ __forceinline__ void cp16(uint32_t dst, const void* src) {
    asm volatile("cp.async.cg.shared.global [%0], [%1], 16;" :: "r"(dst), "l"(src));
}
__device__ __forceinline__ void cp_commit() {
    asm volatile("cp.async.commit_group;" ::: "memory");
}
template <int N>
__device__ __forceinline__ void cp_wait() {
    asm volatile("cp.async.wait_group %0;" :: "n"(N) : "memory");
}

// ============================================================
// Kernel B: upper-triangle ne @ ne^T (fp8), 4-stage cp.async,
//   exp(2x) row+col sums. 128x128 tile, 256 thr, occ 2.
// ============================================================
__global__ void __launch_bounds__(256, 2) gemm_lse_kernel() {
    extern __shared__ char smem[];
    const uint32_t sb = (uint32_t)__cvta_generic_to_shared(smem);

    const int tid = threadIdx.x;
    const int lane = tid & 31;
    const int wid = tid >> 5;
    const int warp_m = wid >> 1;   // 0..3
    const int warp_n = wid & 1;    // 0..1

    // ---- decode upper-triangle tile index -> (bi, bj), bi <= bj ----
    int t = blockIdx.x;
    int bi = (int)(64.5f - sqrtf(64.5f * 64.5f - 2.0f * (float)t));
    if (bi < 0) bi = 0;
    if (bi > 63) bi = 63;
#define TRI_S(b) ((b) * 64 - ((b) * ((b) - 1)) / 2)
    while (bi > 0 && TRI_S(bi) > t) bi--;
    while (bi < 63 && TRI_S(bi + 1) <= t) bi++;
    const int bj = bi + (t - TRI_S(bi));
    const bool diag = (bi == bj);

    const uint8_t* gA = g_ne + (size_t)bi * BM * DD;
    const uint8_t* gB = g_ne + (size_t)bj * BM * DD;

    // cp.async coords: tile = 128 rows x 64B = 512 x 16B chunks, 2/thread/operand
    const int r0c = tid >> 2;
    const int r1c = (tid + 256) >> 2;
    const int kc0 = (tid & 3) * 16;

    // ldmatrix per-lane addressing (fp8 m16n8k32 fragment order)
    const int lrow = lane & 15;
    const int lkb  = (lane >> 4) * 16;
    const uint32_t aoff0 = (uint32_t)((warp_m * 32 + lrow) * SSTB + lkb);
    const uint32_t aoff1 = aoff0 + 16 * SSTB;
    uint32_t boff[4];
#pragma unroll
    for (int nj = 0; nj < 4; nj++)
        boff[nj] = (uint32_t)((warp_n * 64 + nj * 16 + lrow) * SSTB + lkb) + TILE_SMEM;

    float acc[2][8][4];
#pragma unroll
    for (int mi = 0; mi < 2; mi++)
#pragma unroll
        for (int ni = 0; ni < 8; ni++)
#pragma unroll
            for (int k = 0; k < 4; k++) acc[mi][ni][k] = 0.f;

    // ---- prologue: fill STAGES-1 stages ----
#pragma unroll
    for (int p = 0; p < STAGES - 1; p++) {
        uint32_t base = sb + p * STAGE_SMEM;
        cp16(base + r0c * SSTB + kc0, gA + (size_t)r0c * DD + p * BKB + kc0);
        cp16(base + r1c * SSTB + kc0, gA + (size_t)r1c * DD + p * BKB + kc0);
        cp16(base + TILE_SMEM + r0c * SSTB + kc0, gB + (size_t)r0c * DD + p * BKB + kc0);
        cp16(base + TILE_SMEM + r1c * SSTB + kc0, gB + (size_t)r1c * DD + p * BKB + kc0);
        cp_commit();
    }

    for (int kt = 0; kt < NKT; kt++) {
        cp_wait<STAGES - 2>();
        __syncthreads();   // stage kt ready; everyone done with stage kt-1

        int kl = kt + STAGES - 1;
        if (kl < NKT) {
            uint32_t base = sb + (kl & (STAGES - 1)) * STAGE_SMEM;
            cp16(base + r0c * SSTB + kc0, gA + (size_t)r0c * DD + kl * BKB + kc0);
            cp16(base + r1c * SSTB + kc0, gA + (size_t)r1c * DD + kl * BKB + kc0);
            cp16(base + TILE_SMEM + r0c * SSTB + kc0, gB + (size_t)r0c * DD + kl * BKB + kc0);
            cp16(base + TILE_SMEM + r1c * SSTB + kc0, gB + (size_t)r1c * DD + kl * BKB + kc0);
        }
        cp_commit();

        uint32_t base = sb + (kt & (STAGES - 1)) * STAGE_SMEM;
#pragma unroll
        for (int ks = 0; ks < 2; ks++) {          // two k=32 halves of the 64B row
            uint32_t a[2][4], b[4][4];
            ldsm_x4(a[0][0], a[0][1], a[0][2], a[0][3], base + aoff0 + ks * 32);
            ldsm_x4(a[1][0], a[1][1], a[1][2], a[1][3], base + aoff1 + ks * 32);
#pragma unroll
            for (int nj = 0; nj < 4; nj++)
                ldsm_x4(b[nj][0], b[nj][1], b[nj][2], b[nj][3], base + boff[nj] + ks * 32);
#pragma unroll
            for (int mi = 0; mi < 2; mi++)
#pragma unroll
                for (int ni = 0; ni < 8; ni++) {
                    // n-octet ni: x4 group ni>>1, sub (ni&1): b0=(r0|r1), b1=(r2|r3)
                    mma_fp8(acc[mi][ni], a[mi], b[ni >> 1][ni & 1], b[ni >> 1][(ni & 1) + 2]);
                }
        }
    }

    // ---- epilogue: exp(2x); row sums always, col sums if off-diagonal ----
#pragma unroll
    for (int mi = 0; mi < 2; mi++)
#pragma unroll
        for (int ni = 0; ni < 8; ni++)
#pragma unroll
            for (int k = 0; k < 4; k++) {
                float x = acc[mi][ni][k];
                acc[mi][ni][k] = __expf(x + x);
            }

    float* rowbuf = (float*)smem;               // [2][128]
    float* colbuf = (float*)(smem + 1024);      // [4][128]
    __syncthreads();  // all compute done before aliasing smem

#pragma unroll
    for (int mi = 0; mi < 2; mi++) {
        float r0 = 0.f, r1 = 0.f;
#pragma unroll
        for (int ni = 0; ni < 8; ni++) {
            r0 += acc[mi][ni][0] + acc[mi][ni][1];
            r1 += acc[mi][ni][2] + acc[mi][ni][3];
        }
        r0 += __shfl_xor_sync(0xFFFFFFFFu, r0, 1);
        r0 += __shfl_xor_sync(0xFFFFFFFFu, r0, 2);
        r1 += __shfl_xor_sync(0xFFFFFFFFu, r1, 1);
        r1 += __shfl_xor_sync(0xFFFFFFFFu, r1, 2);
        if ((lane & 3) == 0) {
            int rr = warp_m * 32 + mi * 16 + (lane >> 2);
            rowbuf[warp_n * 128 + rr] = r0;
            rowbuf[warp_n * 128 + rr + 8] = r1;
        }
    }

    if (!diag) {
#pragma unroll
        for (int ni = 0; ni < 8; ni++) {
            float ce = acc[0][ni][0] + acc[0][ni][2] + acc[1][ni][0] + acc[1][ni][2];
            float co = acc[0][ni][1] + acc[0][ni][3] + acc[1][ni][1] + acc[1][ni][3];
            ce += __shfl_xor_sync(0xFFFFFFFFu, ce, 4);
            ce += __shfl_xor_sync(0xFFFFFFFFu, ce, 8);
            ce += __shfl_xor_sync(0xFFFFFFFFu, ce, 16);
            co += __shfl_xor_sync(0xFFFFFFFFu, co, 4);
            co += __shfl_xor_sync(0xFFFFFFFFu, co, 8);
            co += __shfl_xor_sync(0xFFFFFFFFu, co, 16);
            if (lane < 4) {
                int cc = warp_n * 64 + ni * 8 + lane * 2;
                colbuf[warp_m * 128 + cc] = ce;
                colbuf[warp_m * 128 + cc + 1] = co;
            }
        }
    }
    __syncthreads();

    if (tid < 128) {
        g_Spart[bj][bi * BM + tid] = rowbuf[tid] + rowbuf[128 + tid];
        if (!diag)
            g_Spart[bi][bj * BM + tid] =
                colbuf[tid] + colbuf[128 + tid] + colbuf[256 + tid] + colbuf[384 + tid];
    }
}

// ============================================================
// Kernel C1: per-row combine + block partial sum (fixed order)
// ============================================================
__global__ void rowval_kernel() {
    int row = blockIdx.x * 256 + threadIdx.x;
    float s = 0.f;
#pragma unroll 8
    for (int p = 0; p < NBLK; p++) s += g_Spart[p][row];
    float v = logf(s) - 2.f * g_pos[row];
#pragma unroll
    for (int o = 16; o > 0; o >>= 1) v += __shfl_xor_sync(0xFFFFFFFFu, v, o);
    __shared__ float sw[8];
    int t = threadIdx.x;
    if ((t & 31) == 0) sw[t >> 5] = v;
    __syncthreads();
    if (t == 0) {
        float tot = 0.f;
#pragma unroll
        for (int w = 0; w < 8; w++) tot += sw[w];
        g_blocksum[blockIdx.x] = tot;
    }
}

// ============================================================
// Kernel C2: final scalar (32 partials)
// ============================================================
__global__ void final_kernel(float* __restrict__ out) {
    int t = threadIdx.x; // 32
    float s = g_blocksum[t];
#pragma unroll
    for (int o = 16; o > 0; o >>= 1) s += __shfl_xor_sync(0xFFFFFFFFu, s, o);
    if (t == 0) out[0] = s * (1.0f / (2.0f * NR));
}

// ============================================================
extern "C" void kernel_launch(void* const* d_in, const int* in_sizes, int n_in,
                              void* d_out, int out_size) {
    const float* emb = (const float*)d_in[0];
    const float* tgt = (const float*)d_in[1];
    float* out = (float*)d_out;

    cudaFuncSetAttribute(gemm_lse_kernel, cudaFuncAttributeMaxDynamicSharedMemorySize, SMEM_TOTAL);

    norm_kernel<<<NR, 128>>>(emb, tgt);
    gemm_lse_kernel<<<NTRI, 256, SMEM_TOTAL>>>();
    rowval_kernel<<<32, 256>>>();
    final_kernel<<<1, 32>>>(out);
}